// round 1
// baseline (speedup 1.0000x reference)
#include <cuda_runtime.h>

#define SEQ   1024
#define BATCH 512
#define INF   128
#define HID   256

#define K1    128     // rows of W_hh kept in smem (transposed)
#define WPAD  132     // padded row length (33 float4-units, odd -> conflict-free LDS.128)

// ---------------------------------------------------------------------------
// Kernel 1: x_proj[s,b,:] = input[s,b,:] @ W_in + (b_in + b_hh), written into
// d_out's output region (in-place; kernel 2 overwrites with h).
// Thread j holds W_in[:, j] in 128 registers. 8 rows of x staged in smem,
// double-buffered against global loads.
// ---------------------------------------------------------------------------
__global__ void __launch_bounds__(256, 1) xproj_kernel(
    const float* __restrict__ input, const float* __restrict__ Win,
    const float* __restrict__ b_in,  const float* __restrict__ b_hh,
    float* __restrict__ out)
{
    __shared__ float xs[2][8 * INF];
    const int j = threadIdx.x;

    float Wreg[INF];
#pragma unroll
    for (int k = 0; k < INF; ++k) Wreg[k] = Win[k * HID + j];
    const float bias = b_in[j] + b_hh[j];

    const int nchunks = (SEQ * BATCH) / 8;   // 65536 chunks of 8 rows
    int c = blockIdx.x;
    if (c >= nchunks) return;

    // preload first chunk (256 threads x float4 = 8 rows x 128 floats)
    ((float4*)xs[0])[j] = ((const float4*)(input + (long)c * 8 * INF))[j];
    __syncthreads();

    int p = 0;
    while (c < nchunks) {
        const int  cn  = c + gridDim.x;
        const bool has = (cn < nchunks);
        float4 nxt;
        if (has) nxt = ((const float4*)(input + (long)cn * 8 * INF))[j];

        float acc[8];
#pragma unroll
        for (int r = 0; r < 8; ++r) acc[r] = bias;

        const float* xb = xs[p];
#pragma unroll
        for (int k4 = 0; k4 < INF / 4; ++k4) {
#pragma unroll
            for (int r = 0; r < 8; ++r) {
                float4 x4 = ((const float4*)(xb + r * INF))[k4];   // broadcast
                acc[r] = fmaf(Wreg[4 * k4 + 0], x4.x, acc[r]);
                acc[r] = fmaf(Wreg[4 * k4 + 1], x4.y, acc[r]);
                acc[r] = fmaf(Wreg[4 * k4 + 2], x4.z, acc[r]);
                acc[r] = fmaf(Wreg[4 * k4 + 3], x4.w, acc[r]);
            }
        }

        const long base = (long)c * 8;
#pragma unroll
        for (int r = 0; r < 8; ++r) out[(base + r) * HID + j] = acc[r];

        if (has) ((float4*)xs[p ^ 1])[j] = nxt;
        __syncthreads();
        p ^= 1;
        c = cn;
    }
}

// ---------------------------------------------------------------------------
// Kernel 2: recurrent scan. Each CTA owns 4 batch rows for all 1024 steps.
// W_hh hybrid: k<128 transposed in smem (Wt[j][k], pad 132), k>=128 in
// 128 registers/thread (thread j holds W_hh[k][j]).
// h kept in smem packed [k][b0..b3] (float4 per k -> one broadcast load
// feeds 4 accumulators). xp read from d_out (prefetched 1 step ahead),
// h written back over the same location.
// ---------------------------------------------------------------------------
__global__ void __launch_bounds__(256, 1) rnn_scan_kernel(
    float* __restrict__ xo,            // d_out output region (xp in, h out)
    const float* __restrict__ hidden0,
    const float* __restrict__ Whh,
    float* __restrict__ hlast)
{
    extern __shared__ float sm[];
    float* Wt = sm;                    // [HID][WPAD], columns k < K1
    float* ht = sm + HID * WPAD;       // [HID][4]  : ht[k*4 + b]

    const int j  = threadIdx.x;
    const int b0 = blockIdx.x * 4;

    // Wt[jj][k] = Whh[k][jj]  (coalesced global read)
    for (int idx = j; idx < K1 * HID; idx += 256) {
        int k  = idx >> 8;
        int jj = idx & 255;
        Wt[jj * WPAD + k] = Whh[k * HID + jj];
    }
    float Wreg[HID - K1];
#pragma unroll
    for (int r = 0; r < HID - K1; ++r) Wreg[r] = Whh[(K1 + r) * HID + j];

#pragma unroll
    for (int b = 0; b < 4; ++b) ht[j * 4 + b] = hidden0[(b0 + b) * HID + j];
    __syncthreads();

    float xp_cur[4], xp_nxt[4];
#pragma unroll
    for (int b = 0; b < 4; ++b)
        xp_cur[b] = xo[((long)0 * BATCH + b0 + b) * HID + j];

    float hl0 = 0.f, hl1 = 0.f, hl2 = 0.f, hl3 = 0.f;

    for (int t = 0; t < SEQ; ++t) {
        if (t + 1 < SEQ) {
#pragma unroll
            for (int b = 0; b < 4; ++b)
                xp_nxt[b] = xo[((long)(t + 1) * BATCH + b0 + b) * HID + j];
        }

        float a0 = xp_cur[0], a1 = xp_cur[1], a2 = xp_cur[2], a3 = xp_cur[3];
        const float4* ht4 = (const float4*)ht;

        // --- smem half of W_hh (k < K1) ---
#pragma unroll
        for (int k4 = 0; k4 < K1 / 4; ++k4) {
            float4 w4 = *(const float4*)(Wt + j * WPAD + 4 * k4);
            float4 h0 = ht4[4 * k4 + 0];
            a0 = fmaf(w4.x, h0.x, a0); a1 = fmaf(w4.x, h0.y, a1);
            a2 = fmaf(w4.x, h0.z, a2); a3 = fmaf(w4.x, h0.w, a3);
            float4 h1 = ht4[4 * k4 + 1];
            a0 = fmaf(w4.y, h1.x, a0); a1 = fmaf(w4.y, h1.y, a1);
            a2 = fmaf(w4.y, h1.z, a2); a3 = fmaf(w4.y, h1.w, a3);
            float4 h2 = ht4[4 * k4 + 2];
            a0 = fmaf(w4.z, h2.x, a0); a1 = fmaf(w4.z, h2.y, a1);
            a2 = fmaf(w4.z, h2.z, a2); a3 = fmaf(w4.z, h2.w, a3);
            float4 h3 = ht4[4 * k4 + 3];
            a0 = fmaf(w4.w, h3.x, a0); a1 = fmaf(w4.w, h3.y, a1);
            a2 = fmaf(w4.w, h3.z, a2); a3 = fmaf(w4.w, h3.w, a3);
        }
        // --- register half of W_hh (k >= K1) ---
#pragma unroll
        for (int k4 = 0; k4 < (HID - K1) / 4; ++k4) {
            int kk = K1 + 4 * k4;
            float4 h0 = ht4[kk + 0];
            a0 = fmaf(Wreg[4 * k4 + 0], h0.x, a0); a1 = fmaf(Wreg[4 * k4 + 0], h0.y, a1);
            a2 = fmaf(Wreg[4 * k4 + 0], h0.z, a2); a3 = fmaf(Wreg[4 * k4 + 0], h0.w, a3);
            float4 h1 = ht4[kk + 1];
            a0 = fmaf(Wreg[4 * k4 + 1], h1.x, a0); a1 = fmaf(Wreg[4 * k4 + 1], h1.y, a1);
            a2 = fmaf(Wreg[4 * k4 + 1], h1.z, a2); a3 = fmaf(Wreg[4 * k4 + 1], h1.w, a3);
            float4 h2 = ht4[kk + 2];
            a0 = fmaf(Wreg[4 * k4 + 2], h2.x, a0); a1 = fmaf(Wreg[4 * k4 + 2], h2.y, a1);
            a2 = fmaf(Wreg[4 * k4 + 2], h2.z, a2); a3 = fmaf(Wreg[4 * k4 + 2], h2.w, a3);
            float4 h3 = ht4[kk + 3];
            a0 = fmaf(Wreg[4 * k4 + 3], h3.x, a0); a1 = fmaf(Wreg[4 * k4 + 3], h3.y, a1);
            a2 = fmaf(Wreg[4 * k4 + 3], h3.z, a2); a3 = fmaf(Wreg[4 * k4 + 3], h3.w, a3);
        }

        float4 hold = ((const float4*)ht)[j];            // h_old[b0..b3][j]
        float hn0 = 0.8f * hold.x + 0.2f * fmaxf(a0, 0.f);
        float hn1 = 0.8f * hold.y + 0.2f * fmaxf(a1, 0.f);
        float hn2 = 0.8f * hold.z + 0.2f * fmaxf(a2, 0.f);
        float hn3 = 0.8f * hold.w + 0.2f * fmaxf(a3, 0.f);

        // write h over xp location for this step (coalesced)
        long ob = ((long)t * BATCH + b0) * HID + j;
        xo[ob + 0 * HID] = hn0;
        xo[ob + 1 * HID] = hn1;
        xo[ob + 2 * HID] = hn2;
        xo[ob + 3 * HID] = hn3;

        __syncthreads();                                  // all reads of ht done
        ((float4*)ht)[j] = make_float4(hn0, hn1, hn2, hn3);
        __syncthreads();                                  // ht updated for next step

        xp_cur[0] = xp_nxt[0]; xp_cur[1] = xp_nxt[1];
        xp_cur[2] = xp_nxt[2]; xp_cur[3] = xp_nxt[3];

        if (t == SEQ - 1) { hl0 = hn0; hl1 = hn1; hl2 = hn2; hl3 = hn3; }
    }

    hlast[(b0 + 0) * HID + j] = hl0;
    hlast[(b0 + 1) * HID + j] = hl1;
    hlast[(b0 + 2) * HID + j] = hl2;
    hlast[(b0 + 3) * HID + j] = hl3;
}

// ---------------------------------------------------------------------------
extern "C" void kernel_launch(void* const* d_in, const int* in_sizes, int n_in,
                              void* d_out, int out_size) {
    const float* input  = (const float*)d_in[0];
    const float* hidden = (const float*)d_in[1];
    const float* Win    = (const float*)d_in[2];
    const float* b_in   = (const float*)d_in[3];
    const float* Whh    = (const float*)d_in[4];
    const float* b_hh   = (const float*)d_in[5];

    float* out   = (float*)d_out;                          // [SEQ,BATCH,HID]
    float* hlast = out + (long)SEQ * BATCH * HID;          // [BATCH,HID] tail

    xproj_kernel<<<148, 256>>>(input, Win, b_in, b_hh, out);

    const int smem = (HID * WPAD + HID * 4) * (int)sizeof(float);  // 139264 B
    cudaFuncSetAttribute(rnn_scan_kernel,
                         cudaFuncAttributeMaxDynamicSharedMemorySize, smem);
    rnn_scan_kernel<<<BATCH / 4, 256, smem>>>(out, hidden, Whh, hlast);
}

// round 3
// speedup vs baseline: 1.5447x; 1.5447x over previous
#include <cuda_runtime.h>

#define SEQ   1024
#define BATCH 512
#define INF   128
#define HID   256
#define WPAD  132   // padded Wt row length in floats (33 float4-units, odd -> conflict-free)

typedef unsigned long long u64;

// ---- packed f32x2 helpers (Blackwell FFMA2 path) ---------------------------
__device__ __forceinline__ u64 pack2(float lo, float hi) {
    u64 r; asm("mov.b64 %0, {%1, %2};" : "=l"(r) : "f"(lo), "f"(hi)); return r;
}
__device__ __forceinline__ void unpack2(u64 v, float& lo, float& hi) {
    asm("mov.b64 {%0, %1}, %2;" : "=f"(lo), "=f"(hi) : "l"(v));
}
__device__ __forceinline__ u64 ffma2(u64 a, u64 b, u64 c) {
    u64 d; asm("fma.rn.f32x2 %0, %1, %2, %3;" : "=l"(d) : "l"(a), "l"(b), "l"(c));
    return d;
}

// ---------------------------------------------------------------------------
// Kernel 1: x_proj[s,b,:] = input[s,b,:] @ W_in + (b_in + b_hh)  -> d_out
// Thread j holds W_in[:, j] as 64 pre-packed k-pair f32x2 registers.
// 8 rows of x staged in smem (natural layout), double buffered.
// One broadcast LDS.128 feeds 2 FFMA2 (4 FMAs).
// ---------------------------------------------------------------------------
__global__ void __launch_bounds__(256, 1) xproj_kernel(
    const float* __restrict__ input, const float* __restrict__ Win,
    const float* __restrict__ b_in,  const float* __restrict__ b_hh,
    float* __restrict__ out)
{
    __shared__ float xs[2][8 * INF];
    const int j = threadIdx.x;

    u64 W2[INF / 2];                       // (W[2k][j], W[2k+1][j])
#pragma unroll
    for (int k2 = 0; k2 < INF / 2; ++k2)
        W2[k2] = pack2(Win[(2 * k2) * HID + j], Win[(2 * k2 + 1) * HID + j]);
    const float bias = b_in[j] + b_hh[j];

    const int nchunks = (SEQ * BATCH) / 8;
    int c = blockIdx.x;
    if (c >= nchunks) return;

    ((float4*)xs[0])[j] = ((const float4*)(input + (long)c * 8 * INF))[j];
    __syncthreads();

    int p = 0;
    while (c < nchunks) {
        const int  cn  = c + gridDim.x;
        const bool has = (cn < nchunks);
        float4 nxt;
        if (has) nxt = ((const float4*)(input + (long)cn * 8 * INF))[j];

        u64 acc[8];
#pragma unroll
        for (int r = 0; r < 8; ++r) acc[r] = pack2(bias, 0.f);

        const float* xb = xs[p];
#pragma unroll
        for (int k4 = 0; k4 < INF / 4; ++k4) {
#pragma unroll
            for (int r = 0; r < 8; ++r) {
                ulonglong2 h2 = ((const ulonglong2*)(xb + r * INF))[k4]; // broadcast
                acc[r] = ffma2(W2[2 * k4 + 0], h2.x, acc[r]);
                acc[r] = ffma2(W2[2 * k4 + 1], h2.y, acc[r]);
            }
        }

        const long base = (long)c * 8;
#pragma unroll
        for (int r = 0; r < 8; ++r) {
            float lo, hi; unpack2(acc[r], lo, hi);
            out[(base + r) * HID + j] = lo + hi;
        }

        if (has) ((float4*)xs[p ^ 1])[j] = nxt;
        __syncthreads();
        p ^= 1;
        c = cn;
    }
}

// ---------------------------------------------------------------------------
// Kernel 2: recurrent scan. 128 CTAs x 4 batch rows. Thread j = column j.
// W_hh k-pairs: k<128 in 64 f32x2 registers; k>=128 in smem Wt[j][kk]
// (transposed, pad 132 -> conflict-free LDS.128, each = 2 packed pairs).
// h in smem, NATURAL [b][k] layout, double buffered -> 1 barrier/step.
// One broadcast LDS.128 of h feeds 2 FFMA2.
// ---------------------------------------------------------------------------
__global__ void __launch_bounds__(256, 1) rnn_scan_kernel(
    float* __restrict__ xo,            // d_out: xp in, h out (same locations)
    const float* __restrict__ hidden0,
    const float* __restrict__ Whh,
    float* __restrict__ hlast)
{
    extern __shared__ float sm[];
    float* Wt   = sm;                  // [HID][WPAD] : k in [128,256)
    float* hbuf = sm + HID * WPAD;     // 2 x [4][HID]

    const int j  = threadIdx.x;
    const int b0 = blockIdx.x * 4;

    // Wt[jj][kk] = Whh[128+kk][jj]  (coalesced global reads)
    for (int idx = j; idx < 128 * HID; idx += 256) {
        int kk = idx >> 8;
        int jj = idx & 255;
        Wt[jj * WPAD + kk] = Whh[(128 + kk) * HID + jj];
    }
    u64 W2[64];                        // k-pairs for k in [0,128)
#pragma unroll
    for (int k2 = 0; k2 < 64; ++k2)
        W2[k2] = pack2(Whh[(2 * k2) * HID + j], Whh[(2 * k2 + 1) * HID + j]);

    // h buffer 0 <- hidden0, natural [b][k] layout
    for (int idx = j; idx < 4 * HID; idx += 256) {
        int b = idx >> 8;
        int k = idx & 255;
        hbuf[idx] = hidden0[(b0 + b) * HID + k];
    }
    __syncthreads();

    float xp_cur[4], xp_nxt[4];
#pragma unroll
    for (int b = 0; b < 4; ++b)
        xp_cur[b] = xo[(long)(b0 + b) * HID + j];

    float hl[4] = {0.f, 0.f, 0.f, 0.f};
    int p = 0;

    for (int t = 0; t < SEQ; ++t) {
        if (t + 1 < SEQ) {
#pragma unroll
            for (int b = 0; b < 4; ++b)
                xp_nxt[b] = xo[((long)(t + 1) * BATCH + b0 + b) * HID + j];
        }

        const float* hc = hbuf + p * 4 * HID;
        float*       hn = hbuf + (p ^ 1) * 4 * HID;

        u64 acc[4];
#pragma unroll
        for (int b = 0; b < 4; ++b) acc[b] = pack2(xp_cur[b], 0.f);

        // --- register half of W_hh: k in [0,128) ---
#pragma unroll
        for (int k4 = 0; k4 < 32; ++k4) {
#pragma unroll
            for (int b = 0; b < 4; ++b) {
                ulonglong2 h2 = ((const ulonglong2*)(hc + b * HID))[k4]; // broadcast
                acc[b] = ffma2(W2[2 * k4 + 0], h2.x, acc[b]);
                acc[b] = ffma2(W2[2 * k4 + 1], h2.y, acc[b]);
            }
        }
        // --- smem half of W_hh: k in [128,256) ---
#pragma unroll
        for (int k4 = 0; k4 < 32; ++k4) {
            ulonglong2 w2 = ((const ulonglong2*)(Wt + j * WPAD))[k4];    // conflict-free
#pragma unroll
            for (int b = 0; b < 4; ++b) {
                ulonglong2 h2 = ((const ulonglong2*)(hc + b * HID))[32 + k4];
                acc[b] = ffma2(w2.x, h2.x, acc[b]);
                acc[b] = ffma2(w2.y, h2.y, acc[b]);
            }
        }

        // epilogue: h_new = 0.8*h + 0.2*relu(pre)
        const long ob = ((long)t * BATCH + b0) * HID + j;
#pragma unroll
        for (int b = 0; b < 4; ++b) {
            float lo, hi; unpack2(acc[b], lo, hi);
            float pre  = lo + hi;
            float hold = hc[b * HID + j];
            float hnv  = 0.8f * hold + 0.2f * fmaxf(pre, 0.f);
            xo[ob + b * HID] = hnv;
            hn[b * HID + j]  = hnv;
            if (t == SEQ - 1) hl[b] = hnv;
        }

        __syncthreads();               // hn complete before next step reads it
        p ^= 1;
#pragma unroll
        for (int b = 0; b < 4; ++b) xp_cur[b] = xp_nxt[b];
    }

#pragma unroll
    for (int b = 0; b < 4; ++b)
        hlast[(long)(b0 + b) * HID + j] = hl[b];
}

// ---------------------------------------------------------------------------
extern "C" void kernel_launch(void* const* d_in, const int* in_sizes, int n_in,
                              void* d_out, int out_size) {
    const float* input  = (const float*)d_in[0];
    const float* hidden = (const float*)d_in[1];
    const float* Win    = (const float*)d_in[2];
    const float* b_in   = (const float*)d_in[3];
    const float* Whh    = (const float*)d_in[4];
    const float* b_hh   = (const float*)d_in[5];

    float* out   = (float*)d_out;                          // [SEQ,BATCH,HID]
    float* hlast = out + (long)SEQ * BATCH * HID;          // [BATCH,HID] tail

    xproj_kernel<<<148, 256>>>(input, Win, b_in, b_hh, out);

    const int smem = (HID * WPAD + 2 * 4 * HID) * (int)sizeof(float); // 143360 B
    cudaFuncSetAttribute(rnn_scan_kernel,
                         cudaFuncAttributeMaxDynamicSharedMemorySize, smem);
    rnn_scan_kernel<<<BATCH / 4, 256, smem>>>(out, hidden, Whh, hlast);
}